// round 15
// baseline (speedup 1.0000x reference)
#include <cuda_runtime.h>
#include <cstdint>

// FuzzyNeuron via mma.sync tf32 (3xTF32 logw, 1x tf32 z), fused kernel.
// R15: manual ping-pong software pipeline. Chunk j+1's B-fragment LDS and
// all 14 MMAs are issued BEFORE chunk j's epilogue reads its accumulators,
// so each HMMA chain has a full independent chunk between producer and
// consumer (ptxas refused to build this itself in R12/R13; R14 showed full
// unroll w/o pipelining just blows I$). 1 m-tile/warp to fit 2 C buffers
// in the 128-reg budget, 4 CTAs/SM, persistent grid 592.

typedef unsigned int u32;

#define LOG2E 1.4426950408889634f
#define BLOCK 128
#define GRID 592       // 4 CTAs/SM x 148 SMs
#define NTILES 2048    // 131072 / 64 rows per CTA-tile

// fragment-packed B layouts (conflict-free strides)
#define FL(j, ks, tig, g) (((j) * 4 + (ks)) * 40 + (tig) * 10 + (g))   // float4
#define FZ(j, ks, tig, g) (((j) * 2 + (ks)) * 48 + (tig) * 12 + (g))   // float2

__device__ __forceinline__ u32 tf32_bits(float v) {
    u32 r; asm("cvt.rna.tf32.f32 %0, %1;" : "=r"(r) : "f"(v)); return r;
}
__device__ __forceinline__ float exp2_fast(float v) {
    float r; asm("ex2.approx.ftz.f32 %0, %1;" : "=f"(r) : "f"(v)); return r;
}
// non-volatile: pure dataflow
__device__ __forceinline__ void mma8(float* c, const u32* a, u32 b0, u32 b1) {
    asm("mma.sync.aligned.m16n8k8.row.col.f32.tf32.tf32.f32 "
        "{%0,%1,%2,%3}, {%4,%5,%6,%7}, {%8,%9}, {%0,%1,%2,%3};"
        : "+f"(c[0]), "+f"(c[1]), "+f"(c[2]), "+f"(c[3])
        : "r"(a[0]), "r"(a[1]), "r"(a[2]), "r"(a[3]), "r"(b0), "r"(b1));
}

__device__ __forceinline__ float coefL(const float* mu, const float* sigma, int n, int k) {
    if (k < 16) {
        float m = mu[n * 16 + k], s = sigma[n * 16 + k];
        return 2.0f * __fdividef(0.5f, s * s) * m * LOG2E;      // multiplies x
    } else {
        float s = sigma[n * 16 + (k - 16)];
        return -__fdividef(0.5f, s * s) * LOG2E;                // multiplies x^2
    }
}

struct Cfrag { float c1[4], c2[4], c3[4], cz[4]; };

// Issue one chunk's 7 LDS + 14 MMAs (accumulators seeded with f / bias).
__device__ __forceinline__ void chunk_mma(
    Cfrag& C, const u32 ah[4][4], const u32 al[4][4],
    const float4* sBl, const float2* sBz, const float2* sFB,
    int j, int tig, int g) {
    float4 q = *reinterpret_cast<const float4*>(&sFB[8 * j + 2 * tig]); // {f0,b0,f1,b1}
    C.c1[0] = q.x; C.c1[1] = q.z; C.c1[2] = q.x; C.c1[3] = q.z;
    C.cz[0] = q.y; C.cz[1] = q.w; C.cz[2] = q.y; C.cz[3] = q.w;
#pragma unroll
    for (int i = 0; i < 4; i++) { C.c2[i] = 0.f; C.c3[i] = 0.f; }
#pragma unroll
    for (int ks = 0; ks < 4; ks++) {
        float4 Bf = sBl[FL(j, ks, tig, g)];
        u32 bh0 = __float_as_uint(Bf.x), bh1 = __float_as_uint(Bf.y);
        u32 bl0 = __float_as_uint(Bf.z), bl1 = __float_as_uint(Bf.w);
        mma8(C.c1, ah[ks], bh0, bh1);
        mma8(C.c2, al[ks], bh0, bh1);
        mma8(C.c3, ah[ks], bl0, bl1);
    }
#pragma unroll
    for (int ks = 0; ks < 2; ks++) {
        float2 Bz = sBz[FZ(j, ks, tig, g)];
        mma8(C.cz, ah[ks], __float_as_uint(Bz.x), __float_as_uint(Bz.y));
    }
}

// Consume one chunk's accumulators.
__device__ __forceinline__ void chunk_epi(
    const Cfrag& C, float& num0, float& den0, float& num1, float& den1) {
    float w00 = exp2_fast(C.c1[0] + C.c2[0] + C.c3[0]);
    float w01 = exp2_fast(C.c1[1] + C.c2[1] + C.c3[1]);
    float w10 = exp2_fast(C.c1[2] + C.c2[2] + C.c3[2]);
    float w11 = exp2_fast(C.c1[3] + C.c2[3] + C.c3[3]);
    num0 = fmaf(C.cz[0], w00, num0);
    num0 = fmaf(C.cz[1], w01, num0);
    num1 = fmaf(C.cz[2], w10, num1);
    num1 = fmaf(C.cz[3], w11, num1);
    den0 += w00 + w01;
    den1 += w10 + w11;
}

__global__ void __launch_bounds__(BLOCK, 4)
fuzzy_mma_kernel(const float* __restrict__ x,
                 const float* __restrict__ mu,
                 const float* __restrict__ sigma,
                 const float* __restrict__ rho,
                 float* __restrict__ out) {
    __shared__ __align__(16) float4 sBl[8 * 4 * 40];
    __shared__ __align__(8)  float2 sBz[8 * 2 * 48];
    __shared__ __align__(16) float2 sFB[64];

    const int tid = threadIdx.x;
    const int w = tid >> 5, lane = tid & 31;
    const int g = lane >> 2, tig = lane & 3;

    // ---- build fragment-packed B (once per CTA) ----
    for (int i = tid; i < 1024; i += BLOCK) {
        int gg = i & 7, tt = (i >> 3) & 3, ks = (i >> 5) & 3, j = i >> 7;
        int n = j * 8 + gg, k0 = ks * 8 + tt;
        float b0 = coefL(mu, sigma, n, k0);
        float b1 = coefL(mu, sigma, n, k0 + 4);
        float b0h = __uint_as_float(tf32_bits(b0));
        float b1h = __uint_as_float(tf32_bits(b1));
        sBl[FL(j, ks, tt, gg)] = make_float4(b0h, b1h, b0 - b0h, b1 - b1h);
    }
    for (int i = tid; i < 512; i += BLOCK) {
        int gg = i & 7, tt = (i >> 3) & 3, ks = (i >> 5) & 1, j = i >> 6;
        int n = j * 8 + gg, k0 = ks * 8 + tt;
        sBz[FZ(j, ks, tt, gg)] =
            make_float2(__uint_as_float(tf32_bits(rho[n * 17 + k0])),
                        __uint_as_float(tf32_bits(rho[n * 17 + k0 + 4])));
    }
    if (tid < 64) {
        float f = 0.0f;
        for (int a = 0; a < 16; a++) {
            float m = mu[tid * 16 + a], s = sigma[tid * 16 + a];
            f -= m * m * __fdividef(0.5f, s * s);
        }
        sFB[tid] = make_float2(f * LOG2E, rho[tid * 17 + 16]);
    }
    __syncthreads();

    // ---- persistent loop over 64-row tiles (1 m-tile per warp) ----
    for (int t = blockIdx.x; t < NTILES; t += GRID) {
        const int rowBase = t * 64 + w * 16;

        u32 ah[4][4], al[4][4];
#pragma unroll
        for (int rh = 0; rh < 2; rh++) {
            const float* xr = x + (size_t)(rowBase + rh * 8 + g) * 16 + tig;
#pragma unroll
            for (int e = 0; e < 4; e++) {
                float v = xr[4 * e];
                u32 vh = tf32_bits(v);
                u32 vl = tf32_bits(v - __uint_as_float(vh));
                float v2 = v * v;
                u32 v2h = tf32_bits(v2);
                u32 v2l = tf32_bits(v2 - __uint_as_float(v2h));
                int ks = e >> 1;
                int slot = (e & 1) * 2 + rh;
                ah[ks][slot] = vh;      al[ks][slot] = vl;
                ah[2 + ks][slot] = v2h; al[2 + ks][slot] = v2l;
            }
        }

        float num0 = 0.f, den0 = 0.f, num1 = 0.f, den1 = 0.f;

        // ---- software-pipelined chunk loop: MMA(j+1) issued before EPI(j) ----
        Cfrag CA, CB;
        chunk_mma(CA, ah, al, sBl, sBz, sFB, 0, tig, g);
#pragma unroll
        for (int j = 0; j < 8; j += 2) {
            if (j + 1 < 8) chunk_mma(CB, ah, al, sBl, sBz, sFB, j + 1, tig, g);
            chunk_epi(CA, num0, den0, num1, den1);
            if (j + 2 < 8) chunk_mma(CA, ah, al, sBl, sBz, sFB, j + 2, tig, g);
            chunk_epi(CB, num0, den0, num1, den1);
        }

        // ---- reduce across 4 tig lanes; tig==0 writes rows g, g+8 ----
        num0 += __shfl_xor_sync(0xffffffffu, num0, 1);
        den0 += __shfl_xor_sync(0xffffffffu, den0, 1);
        num0 += __shfl_xor_sync(0xffffffffu, num0, 2);
        den0 += __shfl_xor_sync(0xffffffffu, den0, 2);
        num1 += __shfl_xor_sync(0xffffffffu, num1, 1);
        den1 += __shfl_xor_sync(0xffffffffu, den1, 1);
        num1 += __shfl_xor_sync(0xffffffffu, num1, 2);
        den1 += __shfl_xor_sync(0xffffffffu, den1, 2);
        if (tig == 0) {
            out[rowBase + g] = num0 / (den0 + 1e-13f);
            out[rowBase + 8 + g] = num1 / (den1 + 1e-13f);
        }
    }
}

extern "C" void kernel_launch(void* const* d_in, const int* in_sizes, int n_in,
                              void* d_out, int out_size) {
    const float* x = (const float*)d_in[0];      // [N, 16]
    const float* mu = (const float*)d_in[1];     // [64, 16]
    const float* sigma = (const float*)d_in[2];  // [64, 16]
    const float* rho = (const float*)d_in[3];    // [64, 17]
    float* out = (float*)d_out;                  // [N]

    fuzzy_mma_kernel<<<GRID, BLOCK>>>(x, mu, sigma, rho, out);
}

// round 16
// speedup vs baseline: 1.8986x; 1.8986x over previous
#include <cuda_runtime.h>
#include <cstdint>

// FuzzyNeuron via mma.sync tf32 (3xTF32 logw, 1x tf32 z), fused kernel.
// R16: the one untested combination -> 5 CTAs/SM occupancy WITHOUT the
// side effects that sank R11/R14/R15:
//  - 1 m-tile/warp (regs ~90, fits 102-reg cap of launch_bounds(128,5);
//    R11's cap was 80 -> squeezed)
//  - R12 fragment-packed B: 7 LDS/chunk, so LDS-per-row stays at R10's
//    level despite halved per-warp amortization (R11's killer: L1 48%)
//  - rolled chunk loop (L0 I$-safe, unlike R14), no helper structs/fns
//    (R15's spill), straight R12-style inline body.
// Grid 683 persistent: 2048 64-row tiles, ~3 tiles/CTA, single wave.

typedef unsigned int u32;

#define LOG2E 1.4426950408889634f
#define BLOCK 128
#define GRID 683
#define NTILES 2048    // 131072 / 64

// fragment-packed B layouts (conflict-free strides)
#define FL(j, ks, tig, g) (((j) * 4 + (ks)) * 40 + (tig) * 10 + (g))   // float4
#define FZ(j, ks, tig, g) (((j) * 2 + (ks)) * 48 + (tig) * 12 + (g))   // float2

__device__ __forceinline__ u32 tf32_bits(float v) {
    u32 r; asm("cvt.rna.tf32.f32 %0, %1;" : "=r"(r) : "f"(v)); return r;
}
__device__ __forceinline__ float exp2_fast(float v) {
    float r; asm("ex2.approx.ftz.f32 %0, %1;" : "=f"(r) : "f"(v)); return r;
}
// non-volatile: pure dataflow
__device__ __forceinline__ void mma8(float* c, const u32* a, u32 b0, u32 b1) {
    asm("mma.sync.aligned.m16n8k8.row.col.f32.tf32.tf32.f32 "
        "{%0,%1,%2,%3}, {%4,%5,%6,%7}, {%8,%9}, {%0,%1,%2,%3};"
        : "+f"(c[0]), "+f"(c[1]), "+f"(c[2]), "+f"(c[3])
        : "r"(a[0]), "r"(a[1]), "r"(a[2]), "r"(a[3]), "r"(b0), "r"(b1));
}

__device__ __forceinline__ float coefL(const float* mu, const float* sigma, int n, int k) {
    if (k < 16) {
        float m = mu[n * 16 + k], s = sigma[n * 16 + k];
        return 2.0f * __fdividef(0.5f, s * s) * m * LOG2E;      // multiplies x
    } else {
        float s = sigma[n * 16 + (k - 16)];
        return -__fdividef(0.5f, s * s) * LOG2E;                // multiplies x^2
    }
}

__global__ void __launch_bounds__(BLOCK, 5)
fuzzy_mma_kernel(const float* __restrict__ x,
                 const float* __restrict__ mu,
                 const float* __restrict__ sigma,
                 const float* __restrict__ rho,
                 float* __restrict__ out) {
    __shared__ __align__(16) float4 sBl[8 * 4 * 40];   // fragment-packed logw B
    __shared__ __align__(8)  float2 sBz[8 * 2 * 48];   // fragment-packed z B
    __shared__ __align__(16) float2 sFB[64];           // {f*log2e, bias}

    const int tid = threadIdx.x;
    const int w = tid >> 5, lane = tid & 31;
    const int g = lane >> 2, tig = lane & 3;

    // ---- build fragment-packed B (once per CTA) ----
    for (int i = tid; i < 1024; i += BLOCK) {          // Bl: (j,ks,tig,g)
        int gg = i & 7, tt = (i >> 3) & 3, ks = (i >> 5) & 3, j = i >> 7;
        int n = j * 8 + gg, k0 = ks * 8 + tt;
        float b0 = coefL(mu, sigma, n, k0);
        float b1 = coefL(mu, sigma, n, k0 + 4);
        float b0h = __uint_as_float(tf32_bits(b0));
        float b1h = __uint_as_float(tf32_bits(b1));
        sBl[FL(j, ks, tt, gg)] = make_float4(b0h, b1h, b0 - b0h, b1 - b1h);
    }
    for (int i = tid; i < 512; i += BLOCK) {           // Bz: (j,ks,tig,g)
        int gg = i & 7, tt = (i >> 3) & 3, ks = (i >> 5) & 1, j = i >> 6;
        int n = j * 8 + gg, k0 = ks * 8 + tt;
        sBz[FZ(j, ks, tt, gg)] =
            make_float2(__uint_as_float(tf32_bits(rho[n * 17 + k0])),
                        __uint_as_float(tf32_bits(rho[n * 17 + k0 + 4])));
    }
    if (tid < 64) {
        float f = 0.0f;
        for (int a = 0; a < 16; a++) {
            float m = mu[tid * 16 + a], s = sigma[tid * 16 + a];
            f -= m * m * __fdividef(0.5f, s * s);
        }
        sFB[tid] = make_float2(f * LOG2E, rho[tid * 17 + 16]);
    }
    __syncthreads();

    // ---- persistent loop over 64-row tiles (1 m-tile per warp) ----
    for (int t = blockIdx.x; t < NTILES; t += GRID) {
        const int rowBase = t * 64 + w * 16;

        // A fragments: rows {g, g+8}; k-cols tig+4e
        u32 ah[4][4], al[4][4];
#pragma unroll
        for (int rh = 0; rh < 2; rh++) {
            const float* xr = x + (size_t)(rowBase + rh * 8 + g) * 16 + tig;
#pragma unroll
            for (int e = 0; e < 4; e++) {
                float v = xr[4 * e];
                u32 vh = tf32_bits(v);
                u32 vl = tf32_bits(v - __uint_as_float(vh));
                float v2 = v * v;
                u32 v2h = tf32_bits(v2);
                u32 v2l = tf32_bits(v2 - __uint_as_float(v2h));
                int ks = e >> 1;
                int slot = (e & 1) * 2 + rh;
                ah[ks][slot] = vh;      al[ks][slot] = vl;
                ah[2 + ks][slot] = v2h; al[2 + ks][slot] = v2l;
            }
        }

        float num0 = 0.f, den0 = 0.f, num1 = 0.f, den1 = 0.f;

        // ---- 8 rule chunks; 7 LDS at top, 14 MMAs, inline epilogue ----
        for (int j = 0; j < 8; j++) {
            float4 Bf[4];
            float2 Bzf[2];
#pragma unroll
            for (int ks = 0; ks < 4; ks++) Bf[ks] = sBl[FL(j, ks, tig, g)];
#pragma unroll
            for (int ks = 0; ks < 2; ks++) Bzf[ks] = sBz[FZ(j, ks, tig, g)];
            float4 q = *reinterpret_cast<const float4*>(&sFB[8 * j + 2 * tig]); // {f0,b0,f1,b1}

            float c1[4] = {q.x, q.z, q.x, q.z};   // seeded with f
            float c2[4] = {0.f, 0.f, 0.f, 0.f};
            float c3[4] = {0.f, 0.f, 0.f, 0.f};
            float cz[4] = {q.y, q.w, q.y, q.w};   // seeded with bias
#pragma unroll
            for (int ks = 0; ks < 4; ks++) {
                u32 bh0 = __float_as_uint(Bf[ks].x), bh1 = __float_as_uint(Bf[ks].y);
                u32 bl0 = __float_as_uint(Bf[ks].z), bl1 = __float_as_uint(Bf[ks].w);
                mma8(c1, ah[ks], bh0, bh1);
                mma8(c2, al[ks], bh0, bh1);
                mma8(c3, ah[ks], bl0, bl1);
            }
#pragma unroll
            for (int ks = 0; ks < 2; ks++)
                mma8(cz, ah[ks], __float_as_uint(Bzf[ks].x), __float_as_uint(Bzf[ks].y));

            float w00 = exp2_fast(c1[0] + c2[0] + c3[0]);
            float w01 = exp2_fast(c1[1] + c2[1] + c3[1]);
            float w10 = exp2_fast(c1[2] + c2[2] + c3[2]);
            float w11 = exp2_fast(c1[3] + c2[3] + c3[3]);
            num0 = fmaf(cz[0], w00, num0);
            num0 = fmaf(cz[1], w01, num0);
            num1 = fmaf(cz[2], w10, num1);
            num1 = fmaf(cz[3], w11, num1);
            den0 += w00 + w01;
            den1 += w10 + w11;
        }

        // ---- reduce across 4 tig lanes; tig==0 writes rows g, g+8 ----
        num0 += __shfl_xor_sync(0xffffffffu, num0, 1);
        den0 += __shfl_xor_sync(0xffffffffu, den0, 1);
        num0 += __shfl_xor_sync(0xffffffffu, num0, 2);
        den0 += __shfl_xor_sync(0xffffffffu, den0, 2);
        num1 += __shfl_xor_sync(0xffffffffu, num1, 1);
        den1 += __shfl_xor_sync(0xffffffffu, den1, 1);
        num1 += __shfl_xor_sync(0xffffffffu, num1, 2);
        den1 += __shfl_xor_sync(0xffffffffu, den1, 2);
        if (tig == 0) {
            out[rowBase + g] = num0 / (den0 + 1e-13f);
            out[rowBase + 8 + g] = num1 / (den1 + 1e-13f);
        }
    }
}

extern "C" void kernel_launch(void* const* d_in, const int* in_sizes, int n_in,
                              void* d_out, int out_size) {
    const float* x = (const float*)d_in[0];      // [N, 16]
    const float* mu = (const float*)d_in[1];     // [64, 16]
    const float* sigma = (const float*)d_in[2];  // [64, 16]
    const float* rho = (const float*)d_in[3];    // [64, 17]
    float* out = (float*)d_out;                  // [N]

    fuzzy_mma_kernel<<<GRID, BLOCK>>>(x, mu, sigma, rho, out);
}